// round 15
// baseline (speedup 1.0000x reference)
#include <cuda_runtime.h>
#include <cuda_bf16.h>
#include <math.h>
#include <stdint.h>

typedef unsigned long long ull;

// ---------------------------------------------------------------------------
// PSA quaternion block. activations [B=4, C, 4, 1024] fp32 = per-batch
// row-major (C*4) x 1024. 1x1 qconvs -> bf16 split HMMA GEMMs (3-term).
// IQBN stats fused into GEMM epilogue; BN apply fused into consumer prep_x.
// 2-stage cp.async pipeline, 2 CTAs/SM for cross-CTA latency hiding.
// ---------------------------------------------------------------------------

__constant__ int   c_WIDX[16] = {0,1,2,3,  1,0,3,2,  2,3,0,1,  3,2,1,0};
__constant__ float c_SGN [16] = {1,-1,-1,-1,  1,1,1,-1,  1,-1,1,1,  1,1,-1,1};

// ------------------------------ scratch ------------------------------------
__device__ float g_h1 [4*512*1024];
__device__ float g_qkv[4*768*1024];
__device__ float g_o  [4*256*1024];
__device__ float g_o2 [4*256*1024];
__device__ float g_p  [4*256*1024];
__device__ float g_f1 [4*512*1024];
__device__ __nv_bfloat16 g_whp[1048576];
__device__ __nv_bfloat16 g_wlp[1048576];
__device__ __nv_bfloat16 g_xh[4*1024*512];
__device__ __nv_bfloat16 g_xl[4*1024*512];
__device__ float  g_stats[5*1024];
__device__ float4 g_prm [2560];

#define WO_CV1  0
#define WO_QKV  262144
#define WO_PROJ 458752
#define WO_FFN1 524288
#define WO_FFN2 655360
#define WO_CV2  786432
#define SO_BN1  0
#define SO_AN   1024
#define SO_FBN1 2048
#define SO_FBN2 3072
#define SO_BN2  4096
#define PO_BN1  0
#define PO_AN   512
#define PO_FBN1 768
#define PO_FBN2 1280
#define PO_BN2  1536

// --------------------------- helpers ---------------------------------------
__device__ __forceinline__ uint32_t smem_u32(const void* p) {
    uint32_t a;
    asm("{ .reg .u64 t; cvta.to.shared.u64 t, %1; cvt.u32.u64 %0, t; }"
        : "=r"(a) : "l"(p));
    return a;
}
__device__ __forceinline__ void ldm_x4(uint32_t* r, uint32_t addr) {
    asm volatile("ldmatrix.sync.aligned.m8n8.x4.shared.b16 {%0,%1,%2,%3}, [%4];"
                 : "=r"(r[0]), "=r"(r[1]), "=r"(r[2]), "=r"(r[3]) : "r"(addr));
}
__device__ __forceinline__ void mma_bf16(float* c, const uint32_t* a,
                                         uint32_t b0, uint32_t b1) {
    asm volatile(
        "mma.sync.aligned.m16n8k16.row.col.f32.bf16.bf16.f32 "
        "{%0,%1,%2,%3}, {%4,%5,%6,%7}, {%8,%9}, {%0,%1,%2,%3};"
        : "+f"(c[0]), "+f"(c[1]), "+f"(c[2]), "+f"(c[3])
        : "r"(a[0]), "r"(a[1]), "r"(a[2]), "r"(a[3]), "r"(b0), "r"(b1));
}
__device__ __forceinline__ void cpa16(uint32_t sa, const void* g) {
    asm volatile("cp.async.ca.shared.global [%0], [%1], 16;"
                 :: "r"(sa), "l"(g) : "memory");
}
#define CPA_COMMIT() asm volatile("cp.async.commit_group;" ::: "memory")
#define CPA_WAIT(n)  asm volatile("cp.async.wait_group %0;" :: "n"(n) : "memory")

__device__ __forceinline__ ull fma2(ull a, ull b, ull c) {
    ull d; asm("fma.rn.f32x2 %0, %1, %2, %3;" : "=l"(d) : "l"(a), "l"(b), "l"(c));
    return d;
}
__device__ __forceinline__ ull pk2(float lo, float hi) {
    ull r; asm("mov.b64 %0, {%1, %2};" : "=l"(r) : "f"(lo), "f"(hi));
    return r;
}
__device__ __forceinline__ float2 upk2(ull a) {
    float lo, hi; asm("mov.b64 {%0, %1}, %2;" : "=f"(lo), "=f"(hi) : "l"(a));
    return make_float2(lo, hi);
}

// ------------------------- prep kernels ------------------------------------
__global__ void zero_stats() {
    int i = blockIdx.x * blockDim.x + threadIdx.x;
    if (i < 5 * 1024) g_stats[i] = 0.f;
}

__device__ __forceinline__ void expand_one(const float* w, int Cout, int Cin,
                                           int lidx, __nv_bfloat16* wh,
                                           __nv_bfloat16* wl)
{
    int K = Cin * 4;
    int k = lidx % K, m = lidx / K;
    int oc = m >> 2, co = m & 3;
    int ic = k >> 2, ci = k & 3;
    int e = co * 4 + ci;
    float v = c_SGN[e] * w[((size_t)c_WIDX[e] * Cout + oc) * Cin + ic];
    __nv_bfloat16 h = __float2bfloat16(v);
    wh[lidx] = h;
    wl[lidx] = __float2bfloat16(v - __bfloat162float(h));
}

__global__ void prep_w_all(const float* w1, const float* w2, const float* w3,
                           const float* w4, const float* w5, const float* w6)
{
    int i = blockIdx.x * blockDim.x + threadIdx.x;
    if (i >= 1048576) return;
    __nv_bfloat16* wh = g_whp;
    __nv_bfloat16* wl = g_wlp;
    if      (i < WO_QKV)  expand_one(w1, 128, 128, i - WO_CV1,  wh + WO_CV1,  wl + WO_CV1);
    else if (i < WO_PROJ) expand_one(w2, 192,  64, i - WO_QKV,  wh + WO_QKV,  wl + WO_QKV);
    else if (i < WO_FFN1) expand_one(w3,  64,  64, i - WO_PROJ, wh + WO_PROJ, wl + WO_PROJ);
    else if (i < WO_FFN2) expand_one(w4, 128,  64, i - WO_FFN1, wh + WO_FFN1, wl + WO_FFN1);
    else if (i < WO_CV2)  expand_one(w5,  64, 128, i - WO_FFN2, wh + WO_FFN2, wl + WO_FFN2);
    else                  expand_one(w6, 128, 128, i - WO_CV2,  wh + WO_CV2,  wl + WO_CV2);
}

__global__ void fin_bn(const float* __restrict__ stats,
                       const float* __restrict__ g, const float* __restrict__ b,
                       float4* __restrict__ prm, int rows, float rlim)
{
    int r = blockIdx.x * blockDim.x + threadIdx.x;
    if (r >= rows) return;
    float s = stats[2 * r], ss = stats[2 * r + 1];
    float mean = s * (1.f / 4096.f);
    float var  = ss * (1.f / 4096.f) - mean * mean;
    float gg = g[r] * rsqrtf(var + 1e-5f);
    float bb = b[r] - mean * gg;
    prm[r] = make_float4(gg, bb, rlim, 0.f);
}

__global__ __launch_bounds__(256) void prep_x(const float* __restrict__ X,
    const float4* __restrict__ prm,
    __nv_bfloat16* __restrict__ xh, __nv_bfloat16* __restrict__ xl,
    int sbs, int Ktot, int kdst)
{
    __shared__ float t[32][33];
    int k0 = blockIdx.x * 32, n0 = blockIdx.y * 32, b = blockIdx.z;
    const float* Xb = X + (size_t)b * sbs;
    int tid = threadIdx.x;
    int c = tid & 31, rbase = tid >> 5;
#pragma unroll
    for (int r = 0; r < 4; r++) {
        int row = rbase + r * 8;
        t[row][c] = Xb[(size_t)(k0 + row) * 1024 + n0 + c];
    }
    __syncthreads();
    float gg = 1.f, bb = 0.f, rl = -1e30f;
    if (prm) { float4 pr = prm[k0 + c]; gg = pr.x; bb = pr.y; rl = pr.z; }
    size_t ob = (size_t)b * 1024 * Ktot;
#pragma unroll
    for (int r = 0; r < 4; r++) {
        int nl = rbase + r * 8;
        float v = fmaxf(fmaf(gg, t[c][nl], bb), rl);
        __nv_bfloat16 h = __float2bfloat16(v);
        size_t oi = ob + (size_t)(n0 + nl) * Ktot + kdst + k0 + c;
        xh[oi] = h;
        xl[oi] = __float2bfloat16(v - __bfloat162float(h));
    }
}

// ------------------------- mma.sync bf16 GEMM ------------------------------
// CTA 128x128, 8 warps (4m x 2n), warp 32x64, BK=32.
// 2-stage cp.async, 2 CTAs/SM.
#define ROWB   80u
#define BUF_SZ 40960u
#define GEMM_SMEM (2 * 40960)

__device__ __forceinline__ void stage_issue(uint32_t smb, uint32_t boff,
    const __nv_bfloat16* __restrict__ wh, const __nv_bfloat16* __restrict__ wl,
    const __nv_bfloat16* __restrict__ xh, const __nv_bfloat16* __restrict__ xl,
    int K, int m0, int n0, int k0, int tid)
{
#pragma unroll
    for (int i = 0; i < 2; i++) {
        int cch = tid + 256 * i;
        int row = cch >> 2, j = cch & 3;
        uint32_t off = (uint32_t)row * ROWB + (uint32_t)(j << 4);
        size_t ga = (size_t)(m0 + row) * K + k0 + j * 8;
        size_t gb = (size_t)(n0 + row) * K + k0 + j * 8;
        cpa16(smb + boff + off,          wh + ga);
        cpa16(smb + boff + 10240 + off,  wl + ga);
        cpa16(smb + boff + 20480 + off,  xh + gb);
        cpa16(smb + boff + 30720 + off,  xl + gb);
    }
}

__global__ __launch_bounds__(256, 2) void hgemm(
    const __nv_bfloat16* __restrict__ wh, const __nv_bfloat16* __restrict__ wl,
    const __nv_bfloat16* __restrict__ xh_, const __nv_bfloat16* __restrict__ xl_,
    float* __restrict__ Y, const float* __restrict__ bias,
    float* __restrict__ stats, int K, int NS, int out_bs)
{
    extern __shared__ char sm[];
    const int tid  = threadIdx.x;
    const int b    = blockIdx.z;
    const int m0   = blockIdx.y * 128;
    const int n0   = blockIdx.x * 128;
    const __nv_bfloat16* xh = xh_ + (size_t)b * 1024 * K;
    const __nv_bfloat16* xl = xl_ + (size_t)b * 1024 * K;
    float* Yb = Y + (size_t)b * out_bs;
    const uint32_t smb = smem_u32(sm);

    const int lane = tid & 31;
    const int wrp  = tid >> 5;
    const int wm   = (wrp & 3) << 5;
    const int wn   = (wrp >> 2) << 6;

    float acc[2][8][4];
#pragma unroll
    for (int i = 0; i < 2; i++)
#pragma unroll
        for (int j = 0; j < 8; j++)
#pragma unroll
            for (int q = 0; q < 4; q++) acc[i][j][q] = 0.f;

    const int a_row = (lane & 15);
    const int a_kc  = (lane >> 4) << 3;
    const int b_row = (lane & 7) + ((lane >> 4) << 3);
    const int b_kc  = ((lane >> 3) & 1) << 3;

    stage_issue(smb, 0, wh, wl, xh, xl, K, m0, n0, 0, tid);
    CPA_COMMIT();
    if (1 < NS) {
        stage_issue(smb, BUF_SZ, wh, wl, xh, xl, K, m0, n0, 32, tid);
        CPA_COMMIT();
    }

    for (int s = 0; s < NS; s++) {
        if (s + 1 < NS) { CPA_WAIT(1); } else { CPA_WAIT(0); }
        __syncthreads();

        uint32_t base = smb + (uint32_t)(s & 1) * BUF_SZ;
        uint32_t Ah = base, Al = base + 10240;
        uint32_t Bh = base + 20480, Bl = base + 30720;

#pragma unroll
        for (int kk = 0; kk < 32; kk += 16) {
            uint32_t ah[2][4], al[2][4];
#pragma unroll
            for (int mt = 0; mt < 2; mt++) {
                uint32_t off = (uint32_t)(wm + mt * 16 + a_row) * ROWB +
                               (uint32_t)((kk + a_kc) << 1);
                ldm_x4(ah[mt], Ah + off);
                ldm_x4(al[mt], Al + off);
            }
#pragma unroll
            for (int gp = 0; gp < 2; gp++) {
                // two gt at a time: load 4 B fragments, term-major MMA block
                uint32_t bh[2][4], bl[2][4];
#pragma unroll
                for (int g2 = 0; g2 < 2; g2++) {
                    int gt = gp * 2 + g2;
                    uint32_t off = (uint32_t)(wn + gt * 16 + b_row) * ROWB +
                                   (uint32_t)((kk + b_kc) << 1);
                    ldm_x4(bh[g2], Bh + off);
                    ldm_x4(bl[g2], Bl + off);
                }
                // term 1: Ah*Bh (8 independent accs)
#pragma unroll
                for (int g2 = 0; g2 < 2; g2++)
#pragma unroll
                    for (int mt = 0; mt < 2; mt++)
#pragma unroll
                        for (int h = 0; h < 2; h++)
                            mma_bf16(acc[mt][(gp * 2 + g2) * 2 + h], ah[mt],
                                     bh[g2][2 * h], bh[g2][2 * h + 1]);
                // term 2: Ah*Bl
#pragma unroll
                for (int g2 = 0; g2 < 2; g2++)
#pragma unroll
                    for (int mt = 0; mt < 2; mt++)
#pragma unroll
                        for (int h = 0; h < 2; h++)
                            mma_bf16(acc[mt][(gp * 2 + g2) * 2 + h], ah[mt],
                                     bl[g2][2 * h], bl[g2][2 * h + 1]);
                // term 3: Al*Bh
#pragma unroll
                for (int g2 = 0; g2 < 2; g2++)
#pragma unroll
                    for (int mt = 0; mt < 2; mt++)
#pragma unroll
                        for (int h = 0; h < 2; h++)
                            mma_bf16(acc[mt][(gp * 2 + g2) * 2 + h], al[mt],
                                     bh[g2][2 * h], bh[g2][2 * h + 1]);
            }
        }
        __syncthreads();
        if (s + 2 < NS) {
            stage_issue(smb, (uint32_t)(s & 1) * BUF_SZ,
                        wh, wl, xh, xl, K, m0, n0, (s + 2) * 32, tid);
            CPA_COMMIT();
        }
    }

#pragma unroll
    for (int mt = 0; mt < 2; mt++) {
        int r0 = m0 + wm + mt * 16 + (lane >> 2);
        int r1 = r0 + 8;
        float bv0 = bias ? bias[r0] : 0.f;
        float bv1 = bias ? bias[r1] : 0.f;
        float* y0 = Yb + (size_t)r0 * 1024;
        float* y1 = Yb + (size_t)r1 * 1024;
        float s0 = 0.f, q0 = 0.f, s1 = 0.f, q1 = 0.f;
#pragma unroll
        for (int nt = 0; nt < 8; nt++) {
            int col = n0 + wn + nt * 8 + ((lane & 3) << 1);
            float* c = acc[mt][nt];
            float v0 = c[0] + bv0, v1 = c[1] + bv0;
            float v2 = c[2] + bv1, v3 = c[3] + bv1;
            *(float2*)(y0 + col) = make_float2(v0, v1);
            *(float2*)(y1 + col) = make_float2(v2, v3);
            s0 += v0 + v1; q0 += v0 * v0 + v1 * v1;
            s1 += v2 + v3; q1 += v2 * v2 + v3 * v3;
        }
        if (stats) {
            s0 += __shfl_xor_sync(0xFFFFFFFF, s0, 1);
            s0 += __shfl_xor_sync(0xFFFFFFFF, s0, 2);
            q0 += __shfl_xor_sync(0xFFFFFFFF, q0, 1);
            q0 += __shfl_xor_sync(0xFFFFFFFF, q0, 2);
            s1 += __shfl_xor_sync(0xFFFFFFFF, s1, 1);
            s1 += __shfl_xor_sync(0xFFFFFFFF, s1, 2);
            q1 += __shfl_xor_sync(0xFFFFFFFF, q1, 1);
            q1 += __shfl_xor_sync(0xFFFFFFFF, q1, 2);
            if ((lane & 3) == 0) {
                atomicAdd(&stats[2 * r0],     s0);
                atomicAdd(&stats[2 * r0 + 1], q0);
                atomicAdd(&stats[2 * r1],     s1);
                atomicAdd(&stats[2 * r1 + 1], q1);
            }
        }
    }
}

// ----------------------------- attention -----------------------------------
__global__ __launch_bounds__(512) void attn_kernel(const float* __restrict__ qkv,
                                                   float* __restrict__ o)
{
    extern __shared__ float smf[];
    float* Ks = smf;
    float* Vs = smf + 16 * 1024;
    int combo = blockIdx.x;
    int qc = combo & 3;
    int hh = (combo >> 2) & 3;
    int bb = combo >> 4;
    int tid = threadIdx.x;
    const size_t cs = 4 * 1024;
    const float* qb = qkv + (((size_t)bb * 192 + hh * 48 +  0) * 4 + qc) * 1024;
    const float* kb = qkv + (((size_t)bb * 192 + hh * 48 + 16) * 4 + qc) * 1024;
    const float* vb = qkv + (((size_t)bb * 192 + hh * 48 + 32) * 4 + qc) * 1024;

    for (int i = tid; i < 16 * 1024; i += 512) {
        int d = i >> 10, m = i & 1023;
        Ks[i] = kb[d * cs + m];
        Vs[i] = vb[d * cs + m];
    }
    __syncthreads();

    int n = blockIdx.y * 512 + tid;
    ull qp[16];
#pragma unroll
    for (int d = 0; d < 16; d++) {
        float qd = qb[d * cs + n] * 0.25f;
        qp[d] = pk2(qd, qd);
    }

    float l = 0.f;
    ull acc2[16];
#pragma unroll
    for (int d = 0; d < 16; d++) acc2[d] = 0ull;

    for (int mv = 0; mv < 256; mv++) {
        ull s01 = 0ull, s23 = 0ull;
#pragma unroll
        for (int d = 0; d < 16; d++) {
            ulonglong2 kv = *(const ulonglong2*)&Ks[d * 1024 + mv * 4];
            s01 = fma2(qp[d], kv.x, s01);
            s23 = fma2(qp[d], kv.y, s23);
        }
        float2 sA = upk2(s01), sB = upk2(s23);
        float p0 = __expf(sA.x);
        float p1 = __expf(sA.y);
        float p2 = __expf(sB.x);
        float p3 = __expf(sB.y);
        l += (p0 + p1) + (p2 + p3);
        ull p01 = pk2(p0, p1), p23 = pk2(p2, p3);
#pragma unroll
        for (int d = 0; d < 16; d++) {
            ulonglong2 vv = *(const ulonglong2*)&Vs[d * 1024 + mv * 4];
            acc2[d] = fma2(p01, vv.x, acc2[d]);
            acc2[d] = fma2(p23, vv.y, acc2[d]);
        }
    }
    float inv = 1.f / l;
#pragma unroll
    for (int d = 0; d < 16; d++) {
        float2 a = upk2(acc2[d]);
        o[(((size_t)bb * 64 + hh * 16 + d) * 4 + qc) * 1024 + n] = (a.x + a.y) * inv;
    }
}

// --------------------- 3x3 grouped quaternion PE conv ----------------------
__global__ __launch_bounds__(1024) void pe_kernel(
    const float* __restrict__ o, const float* __restrict__ pw,
    const float* __restrict__ pb, float* __restrict__ o2)
{
    int blk = blockIdx.x;
    int co = blk & 3;
    int oc = (blk >> 2) & 63;
    int bb = blk >> 8;
    int t = threadIdx.x;
    int y = t >> 5, xq = t & 31;
    int g = oc >> 2;

    float acc = pb[oc * 4 + co];
#pragma unroll
    for (int ci = 0; ci < 4; ci++) {
        int wc  = c_WIDX[co * 4 + ci];
        float s = c_SGN [co * 4 + ci];
#pragma unroll
        for (int ic = 0; ic < 4; ic++) {
            const float* xp = o  + (((size_t)bb * 64 + g * 4 + ic) * 4 + ci) * 1024;
            const float* wp = pw + (((size_t)wc * 64 + oc) * 4 + ic) * 9;
            float sum = 0.f;
#pragma unroll
            for (int ky = 0; ky < 3; ky++) {
                int yy = y + ky - 1;
                if (yy < 0 || yy > 31) continue;
#pragma unroll
                for (int kx = 0; kx < 3; kx++) {
                    int xx = xq + kx - 1;
                    if (xx < 0 || xx > 31) continue;
                    sum += xp[yy * 32 + xx] * wp[ky * 3 + kx];
                }
            }
            acc += s * sum;
        }
    }
    size_t oi = (((size_t)bb * 64 + oc) * 4 + co) * 1024 + t;
    o2[oi] = o[oi] + acc;
}

// ---------------------- final bn apply (bn2) --------------------------------
__global__ void apply_bn(const float* __restrict__ x, float* __restrict__ y,
                         const float4* __restrict__ prm)
{
    int i = blockIdx.x * blockDim.x + threadIdx.x;
    int c4 = (i >> 10) & 511;
    float4 pr = prm[c4];
    y[i] = fmaxf(fmaf(pr.x, x[i], pr.y), pr.z);
}

// ---------------------------------------------------------------------------
extern "C" void kernel_launch(void* const* d_in, const int* in_sizes, int n_in,
                              void* d_out, int out_size)
{
    const float* x      = (const float*)d_in[0];
    const float* cv1_w  = (const float*)d_in[1];
    const float* bn1_g  = (const float*)d_in[2];
    const float* bn1_b  = (const float*)d_in[3];
    const float* qkv_w  = (const float*)d_in[4];
    const float* qkv_b  = (const float*)d_in[5];
    const float* proj_w = (const float*)d_in[6];
    const float* proj_b = (const float*)d_in[7];
    const float* pe_w   = (const float*)d_in[8];
    const float* pe_b   = (const float*)d_in[9];
    const float* an_g   = (const float*)d_in[10];
    const float* an_b   = (const float*)d_in[11];
    const float* ffn1_w = (const float*)d_in[12];
    const float* fbn1_g = (const float*)d_in[13];
    const float* fbn1_b = (const float*)d_in[14];
    const float* ffn2_w = (const float*)d_in[15];
    const float* fbn2_g = (const float*)d_in[16];
    const float* fbn2_b = (const float*)d_in[17];
    const float* cv2_w  = (const float*)d_in[18];
    const float* bn2_g  = (const float*)d_in[19];
    const float* bn2_b  = (const float*)d_in[20];
    float* out = (float*)d_out;

    float *h1, *qkv, *o, *o2, *p, *f1, *stats;
    float4* prm;
    __nv_bfloat16 *wh, *wl, *xh, *xl;
    cudaGetSymbolAddress((void**)&h1,  g_h1);
    cudaGetSymbolAddress((void**)&qkv, g_qkv);
    cudaGetSymbolAddress((void**)&o,   g_o);
    cudaGetSymbolAddress((void**)&o2,  g_o2);
    cudaGetSymbolAddress((void**)&p,   g_p);
    cudaGetSymbolAddress((void**)&f1,  g_f1);
    cudaGetSymbolAddress((void**)&wh,  g_whp);
    cudaGetSymbolAddress((void**)&wl,  g_wlp);
    cudaGetSymbolAddress((void**)&xh,  g_xh);
    cudaGetSymbolAddress((void**)&xl,  g_xl);
    cudaGetSymbolAddress((void**)&stats, g_stats);
    cudaGetSymbolAddress((void**)&prm,   g_prm);

    cudaFuncSetAttribute(hgemm, cudaFuncAttributeMaxDynamicSharedMemorySize,
                         GEMM_SMEM);
    cudaFuncSetAttribute(attn_kernel, cudaFuncAttributeMaxDynamicSharedMemorySize,
                         131072);

    const int BS512 = 512 * 1024;
    const int BS768 = 768 * 1024;
    const int BS256 = 256 * 1024;
    const float NORELU = -1e30f;

    prep_w_all<<<4096, 256>>>(cv1_w, qkv_w, proj_w, ffn1_w, ffn2_w, cv2_w);
    zero_stats<<<20, 256>>>();

    // 1) cv1 -> h1 raw (+bn1 stats)
    prep_x<<<dim3(16, 32, 4), 256>>>(x, nullptr, xh, xl, BS512, 512, 0);
    hgemm<<<dim3(8, 4, 4), 256, GEMM_SMEM>>>(wh + WO_CV1, wl + WO_CV1, xh, xl,
                                             h1, nullptr, stats + SO_BN1,
                                             512, 16, BS512);
    fin_bn<<<4, 128>>>(stats + SO_BN1, bn1_g, bn1_b, prm + PO_BN1, 512, 0.f);

    // 2) qkv = W * relu(bn1(h1[0:256]))
    prep_x<<<dim3(8, 32, 4), 256>>>(h1, prm + PO_BN1, xh, xl, BS512, 256, 0);
    hgemm<<<dim3(8, 6, 4), 256, GEMM_SMEM>>>(wh + WO_QKV, wl + WO_QKV, xh, xl,
                                             qkv, qkv_b, nullptr,
                                             256, 8, BS768);

    // 3) attention -> o
    attn_kernel<<<dim3(64, 2), 512, 131072>>>(qkv, o);

    // 4) o2 = o + pe(o) + pe_b
    pe_kernel<<<1024, 1024>>>(o, pe_w, pe_b, o2);

    // 5) proj(o2) -> p raw (+attn_norm stats)
    prep_x<<<dim3(8, 32, 4), 256>>>(o2, nullptr, xh, xl, BS256, 256, 0);
    hgemm<<<dim3(8, 2, 4), 256, GEMM_SMEM>>>(wh + WO_PROJ, wl + WO_PROJ, xh, xl,
                                             p, proj_b, stats + SO_AN,
                                             256, 8, BS256);
    fin_bn<<<2, 128>>>(stats + SO_AN, an_g, an_b, prm + PO_AN, 256, NORELU);

    // 6) ffn1(attn_norm(p)) -> f1 raw (+fbn1 stats)
    prep_x<<<dim3(8, 32, 4), 256>>>(p, prm + PO_AN, xh, xl, BS256, 256, 0);
    hgemm<<<dim3(8, 4, 4), 256, GEMM_SMEM>>>(wh + WO_FFN1, wl + WO_FFN1, xh, xl,
                                             f1, nullptr, stats + SO_FBN1,
                                             256, 8, BS512);
    fin_bn<<<4, 128>>>(stats + SO_FBN1, fbn1_g, fbn1_b, prm + PO_FBN1, 512, 0.f);

    // 7) ffn2(relu(fbn1(f1))) -> o raw (+fbn2 stats)
    prep_x<<<dim3(16, 32, 4), 256>>>(f1, prm + PO_FBN1, xh, xl, BS512, 512, 0);
    hgemm<<<dim3(8, 2, 4), 256, GEMM_SMEM>>>(wh + WO_FFN2, wl + WO_FFN2, xh, xl,
                                             o, nullptr, stats + SO_FBN2,
                                             512, 16, BS256);
    fin_bn<<<2, 128>>>(stats + SO_FBN2, fbn2_g, fbn2_b, prm + PO_FBN2, 256, NORELU);

    // 8) cv2(concat(fbn2(o), relu(bn1(h1[256:512])))) -> f1 raw (+bn2 stats)
    prep_x<<<dim3(8, 32, 4), 256>>>(o, prm + PO_FBN2, xh, xl, BS256, 512, 0);
    prep_x<<<dim3(8, 32, 4), 256>>>(h1 + 256 * 1024, prm + PO_BN1 + 256,
                                    xh, xl, BS512, 512, 256);
    hgemm<<<dim3(8, 4, 4), 256, GEMM_SMEM>>>(wh + WO_CV2, wl + WO_CV2, xh, xl,
                                             f1, nullptr, stats + SO_BN2,
                                             512, 16, BS512);
    fin_bn<<<4, 128>>>(stats + SO_BN2, bn2_g, bn2_b, prm + PO_BN2, 512, 0.f);

    // 9) out = relu(bn2(f1))
    apply_bn<<<2048, 1024>>>(f1, out, prm + PO_BN2);
}